// round 1
// baseline (speedup 1.0000x reference)
#include <cuda_runtime.h>
#include <math.h>

// Problem constants (fixed by the reference setup)
#define HH 512
#define WW 512
#define NB 8          // batch
#define NIMG 16       // 8 input masks + 8 target masks
#define BIGF 1.0e6f

// Scratch: per mask-image, holds dd (down distance) then f = d1^2 after column pass.
__device__ float g_f[NIMG][HH][WW];          // 16 MB static scratch (no allocs)
__device__ unsigned int g_hmax[NB][2];       // per-batch max(dt^2) bits, [0]=h_ba, [1]=h_ab
__device__ unsigned int g_any[NIMG];         // mask-nonempty flags

// ---------------------------------------------------------------------------
__global__ void init_kernel() {
    int t = threadIdx.x;
    if (t < NB) { g_hmax[t][0] = 0u; g_hmax[t][1] = 0u; }
    if (t < NIMG) g_any[t] = 0u;
}

// ---------------------------------------------------------------------------
// Column pass: exact 1D distance along axis 0 (two scans per column), writes
// f = min(d_down, d_up, BIG)^2 into g_f. One thread per column.
__global__ void col_pass(const float* __restrict__ inA,
                         const float* __restrict__ inB) {
    const int im = blockIdx.y;                       // 0..15
    const int j  = blockIdx.x * blockDim.x + threadIdx.x;  // column 0..511
    const int b  = im & 7;
    const float* src = ((im < NB) ? inA : inB) + (size_t)b * HH * WW;
    float* f = &g_f[im][0][0];

    // down-scan: distance to nearest True at row <= i (mirrors reference:
    // dd = min(i - cummax(pos), BIG) with pos = -BIG when no True yet)
    float lastf = -BIGF;
    bool any = false;
    #pragma unroll 4
    for (int i = 0; i < HH; i++) {
        float v = src[i * WW + j];
        if (v > 0.5f) { lastf = (float)i; any = true; }
        float dd = fminf((float)i - lastf, BIGF);
        f[i * WW + j] = dd;
    }
    // up-scan: combine with distance to nearest True at row >= i
    float nxtf = 2.0e6f;
    #pragma unroll 4
    for (int i = HH - 1; i >= 0; i--) {
        float v = src[i * WW + j];
        if (v > 0.5f) nxtf = (float)i;
        float du = fminf(nxtf - (float)i, BIGF);
        float d1 = fminf(f[i * WW + j], du);
        f[i * WW + j] = d1 * d1;
    }

    unsigned ballot = __ballot_sync(0xffffffffu, any);
    if ((threadIdx.x & 31) == 0 && ballot) atomicOr(&g_any[im], 1u);
}

// ---------------------------------------------------------------------------
// Row pass + masked max-reduction.
// D[i][j] = min_k f[i][k] + (j-k)^2, computed exactly with an adaptive radius:
// best starts at f[j] (k=j); offsets with off^2 >= current best cannot improve.
// Then gate by the OTHER mask and block-reduce the max into g_hmax.
__global__ void row_pass(const float* __restrict__ inA,
                         const float* __restrict__ inB) {
    __shared__ float sm[WW];
    __shared__ float red[8];

    const int im  = blockIdx.y;    // which mask-image's EDT
    const int row = blockIdx.x;    // 0..511
    const int b   = im & 7;
    const int t   = threadIdx.x;   // 256 threads, 2 columns each

    const float* f = &g_f[im][row][0];
    // gate by the OTHER tensor's mask at the same (b, row)
    const float* other = ((im < NB) ? inB : inA) + ((size_t)b * HH + row) * WW;

    sm[t]       = f[t];
    sm[t + 256] = f[t + 256];
    __syncthreads();

    float vmax = 0.0f;
    #pragma unroll
    for (int c = 0; c < 2; c++) {
        int j = t + c * 256;
        float best = sm[j];
        int off = 1;
        while (off < WW) {
            float o2 = (float)(off * off);
            if (o2 >= best) break;               // exact termination
            int jl = j - off, jr = j + off;
            if (jl >= 0) best = fminf(best, sm[jl] + o2);
            if (jr < WW) best = fminf(best, sm[jr] + o2);
            off++;
        }
        if (other[j] > 0.5f) vmax = fmaxf(vmax, best);
    }

    // block max reduce (256 threads = 8 warps)
    #pragma unroll
    for (int o = 16; o > 0; o >>= 1)
        vmax = fmaxf(vmax, __shfl_down_sync(0xffffffffu, vmax, o));
    int lane = t & 31, wid = t >> 5;
    if (lane == 0) red[wid] = vmax;
    __syncthreads();
    if (wid == 0) {
        float v = (lane < 8) ? red[lane] : 0.0f;
        #pragma unroll
        for (int o = 4; o > 0; o >>= 1)
            v = fmaxf(v, __shfl_down_sync(0xffffffffu, v, o));
        if (lane == 0) {
            // im < NB: EDT of mask-a gated by b -> h_ba (slot 1 semantics is
            // symmetric; final takes max of both slots anyway)
            atomicMax(&g_hmax[b][(im < NB) ? 0 : 1], __float_as_uint(v));
        }
    }
}

// ---------------------------------------------------------------------------
__global__ void finalize_kernel(float* __restrict__ out) {
    int t = threadIdx.x;  // 32 threads
    float term = 0.0f;
    if (t < NB) {
        unsigned m = max(g_hmax[t][0], g_hmax[t][1]);
        float h2 = __uint_as_float(m);
        bool empty = !(g_any[t] != 0u && g_any[t + NB] != 0u);
        float hd = sqrtf(h2);
        term = empty ? 1.0f : (1.0f - 1.0f / (1.0f + hd));
    }
    #pragma unroll
    for (int o = 16; o > 0; o >>= 1)
        term += __shfl_down_sync(0xffffffffu, term, o);
    if (t == 0) out[0] = term / (float)NB;
}

// ---------------------------------------------------------------------------
extern "C" void kernel_launch(void* const* d_in, const int* in_sizes, int n_in,
                              void* d_out, int out_size) {
    const float* inputs  = (const float*)d_in[0];
    const float* targets = (const float*)d_in[1];
    float* out = (float*)d_out;

    init_kernel<<<1, 32>>>();
    {
        dim3 grid(WW / 64, NIMG);
        col_pass<<<grid, 64>>>(inputs, targets);
    }
    {
        dim3 grid(HH, NIMG);
        row_pass<<<grid, 256>>>(inputs, targets);
    }
    finalize_kernel<<<1, 32>>>(out);
}

// round 2
// speedup vs baseline: 1.6545x; 1.6545x over previous
#include <cuda_runtime.h>
#include <math.h>

#define HH 512
#define WW 512
#define NB 8           // batch
#define NIMG 16        // 8 input masks + 8 target masks
#define BIGF 1.0e6f
#define NEGS (-0x100000)   // sentinel "no true above"
#define POSS (0x200000)    // sentinel "no true below"
#define ROW_BLOCKS (NIMG * HH)   // 8192

// 16 MB scratch: f = d1^2 per mask-image (no allocations allowed)
__device__ float g_f[NIMG][HH][WW];
// per-block row_pass partial maxes, written unconditionally every replay
__device__ float g_part[NIMG][HH];
// per-(image, col-tile) nonempty flags, written unconditionally
__device__ int g_anyp[NIMG][16];
// last-block-done counter (self-resetting each replay)
__device__ unsigned int g_count = 0;

// ---------------------------------------------------------------------------
// Column pass, parallel-scan formulation.
// Block = (32 columns, 16 row-chunks) = 512 threads. Each thread owns 32 rows
// of one column, bit-packed into a register mask. Chunk first/last-true rows
// go through smem for an exact prefix-max / suffix-min, then dd/du/f are
// reconstructed from registers. One coalesced load sweep + one store sweep.
__global__ __launch_bounds__(512) void col_pass(const float* __restrict__ inA,
                                                const float* __restrict__ inB) {
    const int im   = blockIdx.y;          // 0..15
    const int tile = blockIdx.x;          // 0..15 (32-column tiles)
    const int tx   = threadIdx.x;         // 0..31  column within tile
    const int ty   = threadIdx.y;         // 0..15  row chunk
    const int j    = tile * 32 + tx;
    const int base = ty * 32;
    const int b    = im & 7;
    const float* src = ((im < NB) ? inA : inB) + (size_t)b * HH * WW;

    // load 32 rows of this column; coalesced across tx
    unsigned int mask = 0u;
    #pragma unroll
    for (int i = 0; i < 32; i++) {
        float v = src[(size_t)(base + i) * WW + j];
        mask |= (v > 0.5f ? 1u : 0u) << i;
    }

    // chunk-local last/first true row (global row index), sentinels if empty
    int lastLoc  = mask ? (base + 31 - __clz(mask)) : NEGS;
    int firstLoc = mask ? (base + __ffs(mask) - 1)  : POSS;

    __shared__ int sL[16][33];
    __shared__ int sF[16][33];
    sL[ty][tx] = lastLoc;
    sF[ty][tx] = firstLoc;
    int anyb = __syncthreads_or(mask != 0u);

    // exclusive prefix max of last-true over chunks above; suffix min below.
    // ty is warp-uniform (blockDim.x == 32) -> no divergence.
    int pre = NEGS;
    for (int y = 0; y < ty; y++) pre = max(pre, sL[y][tx]);
    int suf = POSS;
    for (int y = ty + 1; y < 16; y++) suf = min(suf, sF[y][tx]);

    // descending walk: du, keep d_up in registers
    float farr[32];
    int nextf = suf;
    #pragma unroll
    for (int i = 31; i >= 0; i--) {
        int row = base + i;
        if ((mask >> i) & 1u) nextf = row;
        farr[i] = fminf((float)(nextf - row), BIGF);
    }
    // ascending walk: dd, combine, square, store (coalesced across tx)
    float* f = &g_f[im][0][0];
    int lastf = pre;
    #pragma unroll
    for (int i = 0; i < 32; i++) {
        int row = base + i;
        if ((mask >> i) & 1u) lastf = row;
        float d1 = fminf(fminf((float)(row - lastf), BIGF), farr[i]);
        f[(size_t)row * WW + j] = d1 * d1;
    }

    if (tx == 0 && ty == 0) g_anyp[im][tile] = anyb;
}

// ---------------------------------------------------------------------------
// Row pass: exact adaptive-radius lower envelope + masked max. Writes a
// per-block partial; the elected last block reduces everything and emits the
// final scalar (finalize fused in, counter self-resets).
__global__ __launch_bounds__(256) void row_pass(const float* __restrict__ inA,
                                                const float* __restrict__ inB,
                                                float* __restrict__ out) {
    __shared__ float sm[WW];
    __shared__ float red[8];
    __shared__ unsigned int s_old;
    __shared__ float s_hd2[NIMG];

    const int im  = blockIdx.y;    // which EDT image
    const int row = blockIdx.x;    // 0..511
    const int b   = im & 7;
    const int t   = threadIdx.x;   // 256 threads, 2 columns each

    const float* f = &g_f[im][row][0];
    const float* other = ((im < NB) ? inB : inA) + ((size_t)b * HH + row) * WW;

    sm[t]       = f[t];
    sm[t + 256] = f[t + 256];
    __syncthreads();

    float vmax = 0.0f;
    #pragma unroll
    for (int c = 0; c < 2; c++) {
        int j = t + c * 256;
        float best = sm[j];
        int off = 1;
        while (off < WW) {
            float o2 = (float)(off * off);
            if (o2 >= best) break;               // exact termination
            int jl = j - off, jr = j + off;
            if (jl >= 0) best = fminf(best, sm[jl] + o2);
            if (jr < WW) best = fminf(best, sm[jr] + o2);
            off++;
        }
        if (other[j] > 0.5f) vmax = fmaxf(vmax, best);
    }

    // block max reduce
    #pragma unroll
    for (int o = 16; o > 0; o >>= 1)
        vmax = fmaxf(vmax, __shfl_down_sync(0xffffffffu, vmax, o));
    int lane = t & 31, wid = t >> 5;
    if (lane == 0) red[wid] = vmax;
    __syncthreads();
    if (t == 0) {
        float v = red[0];
        #pragma unroll
        for (int w = 1; w < 8; w++) v = fmaxf(v, red[w]);
        g_part[im][row] = v;
        __threadfence();
        s_old = atomicAdd(&g_count, 1u);
    }
    __syncthreads();

    if (s_old != (unsigned)(ROW_BLOCKS - 1)) return;

    // ---- last block: global reduction + finalize ----
    for (int k = 0; k < NIMG; k++) {
        const float* p = &g_part[k][0];
        float v = fmaxf(p[t], p[t + 256]);
        #pragma unroll
        for (int o = 16; o > 0; o >>= 1)
            v = fmaxf(v, __shfl_down_sync(0xffffffffu, v, o));
        if (lane == 0) red[wid] = v;
        __syncthreads();
        if (t == 0) {
            float m = red[0];
            #pragma unroll
            for (int w = 1; w < 8; w++) m = fmaxf(m, red[w]);
            s_hd2[k] = m;
        }
        __syncthreads();
    }

    if (t < 32) {
        float term = 0.0f;
        if (t < NB) {
            float h2 = fmaxf(s_hd2[t], s_hd2[t + NB]);
            int anyA = 0, anyB = 0;
            #pragma unroll
            for (int k = 0; k < 16; k++) {
                anyA |= g_anyp[t][k];
                anyB |= g_anyp[t + NB][k];
            }
            bool empty = !(anyA && anyB);
            float hd = sqrtf(h2);
            term = empty ? 1.0f : (1.0f - 1.0f / (1.0f + hd));
        }
        #pragma unroll
        for (int o = 16; o > 0; o >>= 1)
            term += __shfl_down_sync(0xffffffffu, term, o);
        if (t == 0) {
            out[0] = term / (float)NB;
            g_count = 0u;   // reset for next graph replay (deterministic)
        }
    }
}

// ---------------------------------------------------------------------------
extern "C" void kernel_launch(void* const* d_in, const int* in_sizes, int n_in,
                              void* d_out, int out_size) {
    const float* inputs  = (const float*)d_in[0];
    const float* targets = (const float*)d_in[1];
    float* out = (float*)d_out;

    {
        dim3 grid(16, NIMG);
        dim3 blk(32, 16);
        col_pass<<<grid, blk>>>(inputs, targets);
    }
    {
        dim3 grid(HH, NIMG);
        row_pass<<<grid, 256>>>(inputs, targets, out);
    }
}

// round 3
// speedup vs baseline: 2.5487x; 1.5405x over previous
#include <cuda_runtime.h>
#include <math.h>

#define HH 512
#define WW 512
#define NB 8            // batch
#define NIMG 16         // 8 input masks + 8 target masks
#define SENT 1024       // empty-column sentinel for d1 (1024^2 > 2*511^2)
#define NEGS (-0x100000)
#define POSS (0x200000)
#define ROWPB 8                       // rows per row_pass block
#define RB (NIMG * HH / ROWPB)        // 1024 blocks

// 8 MB scratch: d1 (axis-0 distance) per mask-image, uint16
__device__ __align__(16) unsigned short g_d1[NIMG][HH][WW];
// packed mask bits: [image][row][16 words of 32 cols]
__device__ unsigned int g_mbits[NIMG][HH][16];
// per-(image, col-tile) nonempty flags
__device__ int g_anyp[NIMG][16];
// running max of dt^2 (float bits) per (slot, batch): [0..7]=A-EDT, [8..15]=B-EDT
__device__ unsigned int g_hmax[16];   // zero-init; finalize resets each replay
__device__ unsigned int g_count = 0;  // last-block counter, self-resetting

// ---------------------------------------------------------------------------
// Column pass: parallel chunked scan. Block = (32 cols, 16 row-chunks).
// Emits d1 as u16 and the thresholded mask as packed bits (ballot transpose).
__global__ __launch_bounds__(512) void col_pass(const float* __restrict__ inA,
                                                const float* __restrict__ inB) {
    const int im   = blockIdx.y;
    const int tile = blockIdx.x;          // 0..15
    const int tx   = threadIdx.x;         // 0..31 column-in-tile
    const int ty   = threadIdx.y;         // 0..15 row chunk
    const int j    = tile * 32 + tx;
    const int base = ty * 32;
    const int b    = im & 7;
    const float* src = ((im < NB) ? inA : inB) + (size_t)b * HH * WW;

    unsigned int mask = 0u;
    #pragma unroll
    for (int i = 0; i < 32; i++) {
        float v = src[(size_t)(base + i) * WW + j];
        mask |= (v > 0.5f ? 1u : 0u) << i;
    }

    // ballot transpose: word for (row base+i, cols tile*32..+31)
    unsigned int myword = 0u;
    #pragma unroll
    for (int i = 0; i < 32; i++) {
        unsigned int w = __ballot_sync(0xffffffffu, (mask >> i) & 1u);
        if (i == tx) myword = w;
    }
    g_mbits[im][base + tx][tile] = myword;

    int lastLoc  = mask ? (base + 31 - __clz(mask)) : NEGS;
    int firstLoc = mask ? (base + __ffs(mask) - 1)  : POSS;

    __shared__ int sL[16][33];
    __shared__ int sF[16][33];
    sL[ty][tx] = lastLoc;
    sF[ty][tx] = firstLoc;
    int anyb = __syncthreads_or(mask != 0u);

    int pre = NEGS;
    for (int y = 0; y < ty; y++) pre = max(pre, sL[y][tx]);
    int suf = POSS;
    for (int y = ty + 1; y < 16; y++) suf = min(suf, sF[y][tx]);

    int darr[32];
    int nextf = suf;
    #pragma unroll
    for (int i = 31; i >= 0; i--) {
        int row = base + i;
        if ((mask >> i) & 1u) nextf = row;
        darr[i] = nextf - row;
    }
    int lastf = pre;
    #pragma unroll
    for (int i = 0; i < 32; i++) {
        int row = base + i;
        if ((mask >> i) & 1u) lastf = row;
        int d1 = min(min(row - lastf, darr[i]), SENT);
        g_d1[im][row][j] = (unsigned short)d1;
    }

    if (tx == 0 && ty == 0) g_anyp[im][tile] = anyb;
}

// ---------------------------------------------------------------------------
// Row pass: warp-per-row, gate-first adaptive exact envelope, fused finalize.
__global__ __launch_bounds__(256) void row_pass(float* __restrict__ out) {
    __shared__ unsigned short srow[ROWPB][WW];
    __shared__ unsigned int s_old;

    const int t    = threadIdx.x;
    const int w    = t >> 5;
    const int lane = t & 31;
    const int blk  = blockIdx.x;         // 0..1023
    const int im   = blk >> 6;           // 64 blocks per image
    const int row  = (blk & 63) * ROWPB + w;
    const int b    = im & 7;
    const int oim  = (im < NB) ? im + NB : im - NB;

    // load this row's d1 (1 KB) via 2x uint4 per lane, plus 16 gate words
    const uint4* src = (const uint4*)&g_d1[im][row][0];
    uint4* dst = (uint4*)&srow[w][0];
    dst[lane]      = src[lane];
    dst[lane + 32] = src[lane + 32];
    unsigned int mword = (lane < 16) ? g_mbits[oim][row][lane] : 0u;
    __syncwarp();

    const unsigned short* r = &srow[w][0];
    float vmax = 0.0f;
    #pragma unroll 4
    for (int c = 0; c < 16; c++) {
        unsigned int gw = __shfl_sync(0xffffffffu, mword, c);
        if ((gw >> lane) & 1u) {
            int j = c * 32 + lane;
            float d = (float)r[j];
            float best = d * d;
            int off = 1;
            while (true) {
                float o2 = (float)(off * off);
                if (o2 >= best) break;            // exact termination
                int jl = j - off, jr = j + off;
                if (jl >= 0) { float x = (float)r[jl]; best = fminf(best, fmaf(x, x, o2)); }
                if (jr < WW) { float x = (float)r[jr]; best = fminf(best, fmaf(x, x, o2)); }
                off++;
            }
            vmax = fmaxf(vmax, best);
        }
    }

    #pragma unroll
    for (int o = 16; o > 0; o >>= 1)
        vmax = fmaxf(vmax, __shfl_down_sync(0xffffffffu, vmax, o));
    if (lane == 0 && vmax > 0.0f)
        atomicMax(&g_hmax[((im < NB) ? 0 : 8) + b], __float_as_uint(vmax));

    __syncthreads();
    if (t == 0) {
        __threadfence();
        s_old = atomicAdd(&g_count, 1u);
    }
    __syncthreads();
    if (s_old != (unsigned)(RB - 1)) return;

    // ---- elected last block: finalize + reset for next replay ----
    if (t < 32) {
        float term = 0.0f;
        if (t < NB) {
            unsigned mA = atomicMax(&g_hmax[t], 0u);        // atomic read
            unsigned mB = atomicMax(&g_hmax[t + 8], 0u);
            float h2 = __uint_as_float(max(mA, mB));
            int anyA = 0, anyB = 0;
            #pragma unroll
            for (int k = 0; k < 16; k++) {
                anyA |= g_anyp[t][k];
                anyB |= g_anyp[t + NB][k];
            }
            bool empty = !(anyA && anyB);
            float hd = sqrtf(h2);
            term = empty ? 1.0f : (1.0f - 1.0f / (1.0f + hd));
        }
        #pragma unroll
        for (int o = 16; o > 0; o >>= 1)
            term += __shfl_down_sync(0xffffffffu, term, o);
        if (t < 16) g_hmax[t] = 0u;        // reset after reads above
        if (t == 0) {
            out[0] = term / (float)NB;
            g_count = 0u;
        }
    }
}

// ---------------------------------------------------------------------------
extern "C" void kernel_launch(void* const* d_in, const int* in_sizes, int n_in,
                              void* d_out, int out_size) {
    const float* inputs  = (const float*)d_in[0];
    const float* targets = (const float*)d_in[1];
    float* out = (float*)d_out;

    {
        dim3 grid(16, NIMG);
        dim3 blk(32, 16);
        col_pass<<<grid, blk>>>(inputs, targets);
    }
    row_pass<<<RB, 256>>>(out);
}

// round 4
// speedup vs baseline: 4.1381x; 1.6236x over previous
#include <cuda_runtime.h>
#include <math.h>

#define HH 512
#define WW 512
#define NB 8
#define NIMG 16
#define NBLK 256
#define NTHR 512
#define NW 16            // warps per block

// packed thresholded masks: [image][row][16 words of 32 cols] = 512 KB
__device__ unsigned int g_mbits[NIMG][HH][16];
// per-(image, block-slice) nonempty flags (written unconditionally -> replay safe)
__device__ int g_anyp[NIMG][16];
// running max dt^2 per EDT-image (integer). Reset by finalizer each replay.
__device__ unsigned int g_hmax[NIMG];
// monotonic generation barriers (grow across replays; compare per-generation)
__device__ unsigned int g_bar1 = 0;
__device__ unsigned int g_bar2 = 0;

// nearest set-bit horizontal distance in a 512-bit packed row (clamped 1024)
__device__ __forceinline__ int nearest_dj(const unsigned int* __restrict__ rb, int j) {
    int jw = j >> 5, jb = j & 31;
    unsigned wj = rb[jw];
    int dright = 1 << 20;
    unsigned hi = wj >> jb;
    if (hi) dright = __ffs(hi) - 1;
    else {
        #pragma unroll 4
        for (int w = jw + 1; w < 16; w++) {
            unsigned x = rb[w];
            if (x) { dright = (w << 5) + __ffs(x) - 1 - j; break; }
        }
    }
    int dleft = 1 << 20;
    unsigned lo = jb ? (wj & ((1u << jb) - 1u)) : 0u;
    if (lo) dleft = jb - (31 - __clz(lo));
    else {
        #pragma unroll 4
        for (int w = jw - 1; w >= 0; w--) {
            if ((j - ((w << 5) + 31)) >= dright) break;   // cannot beat right side
            unsigned x = rb[w];
            if (x) { dleft = j - ((w << 5) + 31 - __clz(x)); break; }
        }
    }
    return min(min(dright, dleft), 1024);
}

// exact squared distance for a rare "leftover" pixel (no true in its 3x3)
__device__ __forceinline__ int exact_d2(int im, int row, int j) {
    int best2 = 1 << 19;                 // > 511^2 + 511^2, and 1024^2 > this
    for (int dr = 0; dr < HH; dr++) {
        int dr2 = dr * dr;
        if (dr2 >= best2) break;         // exact termination
        int r = row - dr;
        if (r >= 0) {
            int dj = nearest_dj(g_mbits[im][r], j);
            best2 = min(best2, dr2 + dj * dj);
        }
        if (dr) {
            r = row + dr;
            if (r < HH) {
                int dj = nearest_dj(g_mbits[im][r], j);
                best2 = min(best2, dr2 + dj * dj);
            }
        }
    }
    return best2;
}

__global__ __launch_bounds__(NTHR, 2)
void hausdorff_fused(const float* __restrict__ inA,
                     const float* __restrict__ inB,
                     float* __restrict__ out) {
    __shared__ int s_red[NW];
    const int t    = threadIdx.x;
    const int w    = t >> 5;
    const int lane = t & 31;
    const int blk  = blockIdx.x;
    const int gw   = blk * NW + w;        // 0..4095
    const int im   = gw >> 8;             // 256 warp-units per image
    const int pair = gw & 255;            // 2 rows per warp

    // ---------------- Phase 1: threshold + bit-pack (2 rows per warp) -------
    {
        const int b = im & 7;
        const float* src = ((im < NB) ? inA : inB) + (size_t)b * HH * WW;
        unsigned acc = 0u;
        #pragma unroll
        for (int h = 0; h < 2; h++) {
            int row = pair * 2 + h;
            const float* rp = src + (size_t)row * WW;
            #pragma unroll
            for (int wc = 0; wc < 16; wc++) {
                float v = rp[wc * 32 + lane];
                unsigned word = __ballot_sync(0xffffffffu, v > 0.5f);
                if (lane == 0) g_mbits[im][row][wc] = word;
                acc |= word;
            }
        }
        int anyb = __syncthreads_or(acc != 0u);
        if (t == 0) g_anyp[blk >> 4][blk & 15] = anyb;   // im == blk>>4
    }

    // ---------------- grid barrier (monotonic generation; all blocks resident)
    {
        __syncthreads();
        if (t == 0) {
            __threadfence();
            unsigned old = atomicAdd(&g_bar1, 1u);
            unsigned target = (old / NBLK + 1u) * NBLK;
            while (*(volatile unsigned int*)&g_bar1 < target) { }
            __threadfence();
        }
        __syncthreads();
    }

    // ---------------- Phase 2: tiered exact Hausdorff max -------------------
    {
        const int half = lane >> 4;           // 0 or 1 -> which of the 2 rows
        const int ln   = lane & 15;           // word index within row
        const int row  = pair * 2 + half;
        const int oim  = im ^ 8;              // the gating (other) mask

        unsigned C = g_mbits[im][row][ln];
        unsigned U = (row > 0)      ? g_mbits[im][row - 1][ln] : 0u;
        unsigned D = (row < HH - 1) ? g_mbits[im][row + 1][ln] : 0u;
        unsigned G = g_mbits[oim][row][ln];

        // neighbor words for funnel shifts (zero at row-word boundaries)
        unsigned Cm = __shfl_sync(0xffffffffu, C, (lane + 31) & 31);
        unsigned Cp = __shfl_sync(0xffffffffu, C, (lane + 1) & 31);
        unsigned Um = __shfl_sync(0xffffffffu, U, (lane + 31) & 31);
        unsigned Up = __shfl_sync(0xffffffffu, U, (lane + 1) & 31);
        unsigned Dm = __shfl_sync(0xffffffffu, D, (lane + 31) & 31);
        unsigned Dp = __shfl_sync(0xffffffffu, D, (lane + 1) & 31);
        if (ln == 0)  { Cm = 0u; Um = 0u; Dm = 0u; }
        if (ln == 15) { Cp = 0u; Up = 0u; Dp = 0u; }

        unsigned sC = ((C << 1) | (Cm >> 31)) | ((C >> 1) | (Cp << 31));
        unsigned sU = ((U << 1) | (Um >> 31)) | ((U >> 1) | (Up << 31));
        unsigned sD = ((D << 1) | (Dm >> 31)) | ((D >> 1) | (Dp << 31));

        unsigned e1 = sC | U | D;             // dist^2 == 1 (given not 0)
        unsigned e2 = sU | sD;                // dist^2 == 2 (given not 0/1)
        unsigned covered = C | e1 | e2;
        unsigned leftover = G & ~covered;

        int v = (G & e2 & ~(e1 | C)) ? 2 : ((G & e1 & ~C) ? 1 : 0);

        int j0 = ln * 32;
        while (leftover) {
            int b = __ffs(leftover) - 1;
            leftover &= leftover - 1u;
            v = max(v, exact_d2(im, row, j0 + b));
        }

        // warp max (both halves share the same image slot)
        #pragma unroll
        for (int o = 16; o > 0; o >>= 1)
            v = max(v, __shfl_down_sync(0xffffffffu, v, o));
        if (lane == 0) s_red[w] = v;
        __syncthreads();
        if (t == 0) {
            int m = s_red[0];
            #pragma unroll
            for (int k = 1; k < NW; k++) m = max(m, s_red[k]);
            atomicMax(&g_hmax[blk >> 4], (unsigned)m);   // im == blk>>4
        }
    }

    // ---------------- completion: block 0 finalizes -------------------------
    __syncthreads();
    __shared__ unsigned s_old;
    if (t == 0) {
        __threadfence();
        s_old = atomicAdd(&g_bar2, 1u);
    }
    if (blk != 0) return;
    __syncthreads();
    if (t == 0) {
        unsigned target = (s_old / NBLK + 1u) * NBLK;
        while (*(volatile unsigned int*)&g_bar2 < target) { }
        __threadfence();
    }
    __syncthreads();

    if (t < 32) {
        float term = 0.0f;
        unsigned h2u = 0u;
        int anyA = 0, anyB = 0;
        if (t < NB) {
            h2u = max(g_hmax[t], g_hmax[t + 8]);
            #pragma unroll
            for (int k = 0; k < 16; k++) {
                anyA |= g_anyp[t][k];
                anyB |= g_anyp[t + 8][k];
            }
        }
        __syncwarp();
        if (t < NIMG) g_hmax[t] = 0u;        // reset for next replay
        if (t < NB) {
            bool empty = !(anyA && anyB);
            float hd = sqrtf((float)h2u);
            term = empty ? 1.0f : (1.0f - 1.0f / (1.0f + hd));
        }
        #pragma unroll
        for (int o = 16; o > 0; o >>= 1)
            term += __shfl_down_sync(0xffffffffu, term, o);
        if (t == 0) out[0] = term / (float)NB;
    }
}

extern "C" void kernel_launch(void* const* d_in, const int* in_sizes, int n_in,
                              void* d_out, int out_size) {
    const float* inputs  = (const float*)d_in[0];
    const float* targets = (const float*)d_in[1];
    float* out = (float*)d_out;
    hausdorff_fused<<<NBLK, NTHR>>>(inputs, targets, out);
}